// round 6
// baseline (speedup 1.0000x reference)
#include <cuda_runtime.h>

// UpsampleLayer2D: x[B,R,C,64] -> out[B,2R,2C,16]
// out[b, ro, co, c] = x[b, ro%R, co%C, 4c + q],  q = 2*(ro>=R) + (co>=C)
//
// R6: persistent grid-stride version of R1's proven layout.
// 4 threads per input pixel (role t): thread loads channels [16t,16t+16) as
// 4 front-batched LDG.128 (warp = 2KB contiguous read), and stores one
// lane-contiguous STG.128 per quadrant (warp = 512B contiguous per stream).
// Grid = 152 SMs x 8 resident CTAs => zero CTA churn / wave transitions.
// 32-bit offset arithmetic (all tensors < 2^31 elements).

#define B_  32
#define R_  200
#define C_  200
#define NPIX (B_ * R_ * C_)          // 1,280,000
#define NGROUPS (NPIX * 4)           // 5,120,000 (pixel,role) items
#define GRID 1216                    // 152 SMs * 8 CTAs
#define TPB  256

__device__ __forceinline__ float comp(const float4& v, int q) {
    switch (q) {
        case 0:  return v.x;
        case 1:  return v.y;
        case 2:  return v.z;
        default: return v.w;
    }
}

__global__ __launch_bounds__(TPB)
void upsample_kernel(const float* __restrict__ in, float* __restrict__ out) {
    const unsigned stride = GRID * TPB;           // 311,296
    const float4* __restrict__ ibase = reinterpret_cast<const float4*>(in);
    float4* __restrict__ op = reinterpret_cast<float4*>(out);

    for (unsigned idx = blockIdx.x * TPB + threadIdx.x; idx < NGROUPS; idx += stride) {
        const unsigned t   = idx & 3u;
        const unsigned pix = idx >> 2;

        const unsigned col = pix % C_;
        const unsigned tmp = pix / C_;
        const unsigned row = tmp % R_;
        const unsigned b   = tmp / R_;

        // Contiguous 64B read: channels [16t, 16t+16)
        const float4* ip = ibase + pix * 16u + t * 4u;
        float4 v0 = __ldcs(ip + 0);
        float4 v1 = __ldcs(ip + 1);
        float4 v2 = __ldcs(ip + 2);
        float4 v3 = __ldcs(ip + 3);

        #pragma unroll
        for (int q = 0; q < 4; q++) {
            const unsigned ro = row + R_ * (q >> 1);
            const unsigned co = col + C_ * (q & 1);
            const unsigned obase = ((b * (2u * R_) + ro) * (2u * C_) + co) * 4u + t;
            float4 w;
            w.x = comp(v0, q);
            w.y = comp(v1, q);
            w.z = comp(v2, q);
            w.w = comp(v3, q);
            __stcs(op + obase, w);
        }
    }
}

extern "C" void kernel_launch(void* const* d_in, const int* in_sizes, int n_in,
                              void* d_out, int out_size) {
    const float* x = (const float*)d_in[0];
    float* out = (float*)d_out;
    upsample_kernel<<<GRID, TPB>>>(x, out);
}

// round 7
// speedup vs baseline: 1.1089x; 1.1089x over previous
#include <cuda_runtime.h>

// UpsampleLayer2D: x[B,R,C,64] -> out[B,2R,2C,16]
// out[b, ro, co, c] = x[b, ro%R, co%C, 4c + q],  q = 2*(ro>=R) + (co>=C)
//
// R7 (final): champion R2 structure, micro-cleaned.
// 4 threads per input pixel (role t): thread loads channels [16t,16t+16) as
// 4 front-batched LDG.128 (warp = 2KB fully-contiguous read), stores one
// lane-contiguous STG.128 per quadrant (warp = 512B contiguous per stream).
// 2 far-apart items per thread for MLP=8; streaming cache hints (single-touch
// data); exact grid (no tail branch); 32-bit offset arithmetic.
//
// Measured at the practical HBM3e ceiling for this permutation
// (~83% dram__cycles_active, 6.6 TB/s); all structural variants tested in
// R3-R6 regressed. Traffic is irreducible (655 MB single-touch).

#define B_  32
#define R_  200
#define C_  200
#define NPIX    (B_ * R_ * C_)       // 1,280,000
#define NGROUPS (NPIX * 4)           // 5,120,000 (pixel,role) items
#define HALF    (NGROUPS / 2)        // 2,560,000
#define TPB     256
#define GRID    (HALF / TPB)         // 10000, exact

__device__ __forceinline__ float comp(const float4& v, int q) {
    switch (q) {
        case 0:  return v.x;
        case 1:  return v.y;
        case 2:  return v.z;
        default: return v.w;
    }
}

__device__ __forceinline__ void scatter(unsigned idx, const float4 v[4],
                                        float4* __restrict__ op) {
    const unsigned t   = idx & 3u;
    const unsigned pix = idx >> 2;
    const unsigned col = pix % C_;
    const unsigned tmp = pix / C_;
    const unsigned row = tmp % R_;
    const unsigned b   = tmp / R_;

    #pragma unroll
    for (int q = 0; q < 4; q++) {
        const unsigned ro = row + R_ * (q >> 1);
        const unsigned co = col + C_ * (q & 1);
        const unsigned obase = ((b * (2u * R_) + ro) * (2u * C_) + co) * 4u + t;
        float4 w;
        w.x = comp(v[0], q);
        w.y = comp(v[1], q);
        w.z = comp(v[2], q);
        w.w = comp(v[3], q);
        __stcs(op + obase, w);
    }
}

__global__ __launch_bounds__(TPB)
void upsample_kernel(const float* __restrict__ in, float* __restrict__ out) {
    const unsigned idx  = blockIdx.x * TPB + threadIdx.x;   // < HALF, exact
    const unsigned idx2 = idx + (unsigned)HALF;

    const float4* __restrict__ ibase = reinterpret_cast<const float4*>(in);
    float4* __restrict__ op = reinterpret_cast<float4*>(out);

    // Front-batch all 8 LDG.128 for maximum memory-level parallelism.
    const float4* ip0 = ibase + (idx  >> 2) * 16u + (idx  & 3u) * 4u;
    const float4* ip1 = ibase + (idx2 >> 2) * 16u + (idx2 & 3u) * 4u;

    float4 a[4], b[4];
    a[0] = __ldcs(ip0 + 0);
    a[1] = __ldcs(ip0 + 1);
    a[2] = __ldcs(ip0 + 2);
    a[3] = __ldcs(ip0 + 3);
    b[0] = __ldcs(ip1 + 0);
    b[1] = __ldcs(ip1 + 1);
    b[2] = __ldcs(ip1 + 2);
    b[3] = __ldcs(ip1 + 3);

    scatter(idx,  a, op);
    scatter(idx2, b, op);
}

extern "C" void kernel_launch(void* const* d_in, const int* in_sizes, int n_in,
                              void* d_out, int out_size) {
    const float* x = (const float*)d_in[0];
    float* out = (float*)d_out;
    upsample_kernel<<<GRID, TPB>>>(x, out);
}

// round 8
// speedup vs baseline: 1.1165x; 1.0068x over previous
#include <cuda_runtime.h>

// UpsampleLayer2D: x[B,R,C,64] -> out[B,2R,2C,16]
// out[b, ro, co, c] = x[b, ro%R, co%C, 4c + q],  q = 2*(ro>=R) + (co>=C)
//
// R8 (final): R1's champion layout + exact grid + 32-bit arithmetic,
// no cache hints (hint-bearing variants trended marginally lower DRAM%).
//
// 4 threads per input pixel (role t):
//   load : channels [16t,16t+16) as 4 front-batched LDG.128
//          -> warp reads 2KB fully contiguous, sector-perfect.
//   store: per quadrant one lane-contiguous STG.128
//          -> warp writes 512B contiguous per quadrant stream, full 128B
//             lines covered (no RFO).
//
// Measured ceiling for this pure permutation: ~83% dram__cycles_active,
// 6.6 TB/s on 655 MB irreducible single-touch traffic. Variants tested and
// regressed: 256-bit v8 ops (R3), half-pixel threads (R4), row-aligned fat
// blocks (R5), persistent grid-stride (R6).

#define B_  32
#define R_  200
#define C_  200
#define NPIX    (B_ * R_ * C_)       // 1,280,000
#define NGROUPS (NPIX * 4)           // 5,120,000 (pixel,role) items
#define TPB     256
#define GRID    (NGROUPS / TPB)      // 20000, exact

__device__ __forceinline__ float comp(const float4& v, int q) {
    switch (q) {
        case 0:  return v.x;
        case 1:  return v.y;
        case 2:  return v.z;
        default: return v.w;
    }
}

__global__ __launch_bounds__(TPB)
void upsample_kernel(const float* __restrict__ in, float* __restrict__ out) {
    const unsigned idx = blockIdx.x * TPB + threadIdx.x;   // < NGROUPS, exact

    const unsigned t   = idx & 3u;      // role: input channels [16t, 16t+16)
    const unsigned pix = idx >> 2;

    const unsigned col = pix % C_;
    const unsigned tmp = pix / C_;
    const unsigned row = tmp % R_;
    const unsigned b   = tmp / R_;

    // Contiguous 64B read: channels [16t, 16t+16), front-batched.
    const float4* ip = reinterpret_cast<const float4*>(in) + pix * 16u + t * 4u;
    float4 v0 = ip[0];
    float4 v1 = ip[1];
    float4 v2 = ip[2];
    float4 v3 = ip[3];

    float4* op = reinterpret_cast<float4*>(out);

    #pragma unroll
    for (int q = 0; q < 4; q++) {
        const unsigned ro = row + R_ * (q >> 1);
        const unsigned co = col + C_ * (q & 1);
        const unsigned obase = ((b * (2u * R_) + ro) * (2u * C_) + co) * 4u + t;
        float4 w;
        w.x = comp(v0, q);
        w.y = comp(v1, q);
        w.z = comp(v2, q);
        w.w = comp(v3, q);
        op[obase] = w;
    }
}

extern "C" void kernel_launch(void* const* d_in, const int* in_sizes, int n_in,
                              void* d_out, int out_size) {
    const float* x = (const float*)d_in[0];
    float* out = (float*)d_out;
    upsample_kernel<<<GRID, TPB>>>(x, out);
}

// round 9
// speedup vs baseline: 1.1216x; 1.0046x over previous
#include <cuda_runtime.h>

// UpsampleLayer2D: x[B,R,C,64] -> out[B,2R,2C,16]
// out[b, ro, co, c] = x[b, ro%R, co%C, 4c + q],  q = 2*(ro>=R) + (co>=C)
//
// R9: champion warp-level layout (R1/R8), block size 1024.
// Per-thread code identical to R8; a block now covers 256 contiguous pixels:
//   read : 16KB fully contiguous per block (warp = 2KB, sector-perfect)
//   write: four 4KB contiguous quadrant streams per block (warp-instruction =
//          512B lane-contiguous, full 128B lines covered -> no RFO)
// vs 1KB quadrant streams at TPB=256 — longer DRAM page runs per stream.

#define B_  32
#define R_  200
#define C_  200
#define NPIX    (B_ * R_ * C_)       // 1,280,000
#define NGROUPS (NPIX * 4)           // 5,120,000 (pixel,role) items
#define TPB     1024
#define GRID    (NGROUPS / TPB)      // 5000, exact

__device__ __forceinline__ float comp(const float4& v, int q) {
    switch (q) {
        case 0:  return v.x;
        case 1:  return v.y;
        case 2:  return v.z;
        default: return v.w;
    }
}

__global__ __launch_bounds__(TPB)
void upsample_kernel(const float* __restrict__ in, float* __restrict__ out) {
    const unsigned idx = blockIdx.x * TPB + threadIdx.x;   // < NGROUPS, exact

    const unsigned t   = idx & 3u;      // role: input channels [16t, 16t+16)
    const unsigned pix = idx >> 2;

    const unsigned col = pix % C_;
    const unsigned tmp = pix / C_;
    const unsigned row = tmp % R_;
    const unsigned b   = tmp / R_;

    // Contiguous 64B read: channels [16t, 16t+16), front-batched.
    const float4* ip = reinterpret_cast<const float4*>(in) + pix * 16u + t * 4u;
    float4 v0 = ip[0];
    float4 v1 = ip[1];
    float4 v2 = ip[2];
    float4 v3 = ip[3];

    float4* op = reinterpret_cast<float4*>(out);

    #pragma unroll
    for (int q = 0; q < 4; q++) {
        const unsigned ro = row + R_ * (q >> 1);
        const unsigned co = col + C_ * (q & 1);
        const unsigned obase = ((b * (2u * R_) + ro) * (2u * C_) + co) * 4u + t;
        float4 w;
        w.x = comp(v0, q);
        w.y = comp(v1, q);
        w.z = comp(v2, q);
        w.w = comp(v3, q);
        op[obase] = w;
    }
}

extern "C" void kernel_launch(void* const* d_in, const int* in_sizes, int n_in,
                              void* d_out, int out_size) {
    const float* x = (const float*)d_in[0];
    float* out = (float*)d_out;
    upsample_kernel<<<GRID, TPB>>>(x, out);
}